// round 3
// baseline (speedup 1.0000x reference)
#include <cuda_runtime.h>
#include <math.h>

#define BB 64
#define TT 512
#define FF 64
#define EE 256
#define HH 512
#define GG 2048   // 4*H
#define OO 128

// Scratch (device globals: allocation-free per harness rules)
__device__ float g_xg[(size_t)TT * BB * GG];   // [t][b][g]  256 MB
__device__ float g_Wc[GG * FF];                // fused W_ih @ W_emb  [2048,64]
__device__ float g_biasc[GG];
__device__ float g_h[2][BB * HH];              // double-buffered hidden state
__device__ float g_c[BB * HH];
__device__ float g_hsum[BB * HH];

// ---------------- 1. fuse weights: Wc = W_ih @ W_emb, biasc = W_ih@b_emb + b_ih + b_hh
__global__ void fuse_weights_kernel(const float* __restrict__ Wih,
                                    const float* __restrict__ Wemb,
                                    const float* __restrict__ bemb,
                                    const float* __restrict__ bih,
                                    const float* __restrict__ bhh) {
    int g = blockIdx.x;          // 0..2047
    int f = threadIdx.x;         // 0..63
    __shared__ float s[EE];
    for (int e = f; e < EE; e += 64) s[e] = Wih[g * EE + e];
    __syncthreads();
    float acc = 0.f;
#pragma unroll 8
    for (int e = 0; e < EE; e++) acc += s[e] * Wemb[e * FF + f];
    g_Wc[g * FF + f] = acc;
    if (f == 0) {
        float bb = 0.f;
        for (int e = 0; e < EE; e++) bb += s[e] * bemb[e];
        g_biasc[g] = bb + bih[g] + bhh[g];
    }
}

// ---------------- 2. xg = x @ Wc^T + biasc   (M=32768, N=2048, K=64), out layout [t][b][g]
__global__ __launch_bounds__(256) void xg_kernel(const float* __restrict__ x) {
    __shared__ __align__(16) float xs[FF][68];   // [k][row]
    __shared__ __align__(16) float ws[FF][68];   // [k][col]
    int rbase = blockIdx.x * 64;
    int cbase = blockIdx.y * 64;
    int tid = threadIdx.x;
#pragma unroll
    for (int i = 0; i < 16; i++) {
        int idx = i * 256 + tid;
        int r = idx >> 6, k = idx & 63;
        xs[k][r] = x[(size_t)(rbase + r) * FF + k];
        ws[k][r] = g_Wc[(size_t)(cbase + r) * FF + k];
    }
    __syncthreads();
    int rg = tid & 15, cg = tid >> 4;
    int r0 = rg * 4, c0 = cg * 4;
    float acc[4][4] = {};
#pragma unroll 4
    for (int k = 0; k < FF; k++) {
        float4 hv = *(const float4*)&xs[k][r0];
        float4 wv = *(const float4*)&ws[k][c0];
        float hvv[4] = {hv.x, hv.y, hv.z, hv.w};
        float wvv[4] = {wv.x, wv.y, wv.z, wv.w};
#pragma unroll
        for (int i = 0; i < 4; i++)
#pragma unroll
            for (int j = 0; j < 4; j++) acc[i][j] += hvv[i] * wvv[j];
    }
#pragma unroll
    for (int i = 0; i < 4; i++) {
        int r = rbase + r0 + i;
        int b = r >> 9, t = r & 511;
        float* orow = g_xg + ((size_t)t * BB + b) * GG + cbase;
#pragma unroll
        for (int j = 0; j < 4; j++)
            orow[c0 + j] = acc[i][j] + g_biasc[cbase + c0 + j];
    }
}

// ---------------- 3. init state
__global__ void init_state_kernel() {
    int i = blockIdx.x * blockDim.x + threadIdx.x;
    if (i < BB * HH) {
        g_h[0][i] = 0.f;
        g_c[i] = 0.f;
        g_hsum[i] = 0.f;
    }
}

// ---------------- 4. one LSTM step: gates = xg[t] + h @ W_hh^T ; activations ; update h,c,hsum
// grid = 128 blocks (4 hidden indices each), 256 threads = 64 tile-threads x 4 k-groups
__global__ __launch_bounds__(256) void lstm_step_kernel(const float* __restrict__ Whh, int t) {
    __shared__ __align__(16) float hs[64][68];   // [k][b]  k-major
    __shared__ __align__(16) float ws[64][20];   // [k][c], c = gate*4 + jj
    __shared__ float red[4][64][16];             // k-group partials

    const float* hin = g_h[t & 1];
    float* hout = g_h[(t + 1) & 1];

    int j0 = blockIdx.x * 4;
    int tid = threadIdx.x;
    int kg = tid >> 6;          // 0..3  (k-split group)
    int tt = tid & 63;          // tile-thread
    int rg = tt & 15, cg = tt >> 4;
    int r0 = rg * 4, c0 = cg * 4;

    float acc[4][4] = {};

    for (int chunk = 0; chunk < 8; chunk++) {
        int k0 = chunk * 64;
#pragma unroll
        for (int i = 0; i < 16; i++) {
            int idx = i * 256 + tid;
            int r = idx >> 6, k = idx & 63;
            hs[k][r] = hin[r * HH + k0 + k];
        }
#pragma unroll
        for (int i = 0; i < 4; i++) {
            int idx = i * 256 + tid;
            int c = idx >> 6, k = idx & 63;
            int wrow = (c >> 2) * HH + j0 + (c & 3);
            ws[k][c] = Whh[(size_t)wrow * HH + k0 + k];
        }
        __syncthreads();
        int ks = kg * 16;
#pragma unroll
        for (int k = ks; k < ks + 16; k++) {
            float4 hv = *(const float4*)&hs[k][r0];
            float4 wv = *(const float4*)&ws[k][c0];
            float hvv[4] = {hv.x, hv.y, hv.z, hv.w};
            float wvv[4] = {wv.x, wv.y, wv.z, wv.w};
#pragma unroll
            for (int i = 0; i < 4; i++)
#pragma unroll
                for (int j = 0; j < 4; j++) acc[i][j] += hvv[i] * wvv[j];
        }
        __syncthreads();
    }

    // write k-group partials
#pragma unroll
    for (int i = 0; i < 4; i++)
#pragma unroll
        for (int j = 0; j < 4; j++) red[kg][r0 + i][c0 + j] = acc[i][j];
    __syncthreads();

    // epilogue: one thread per (batch b, local hidden jj)
    int b = tid >> 2, jj = tid & 3;
    float gi = 0.f, gf = 0.f, gg = 0.f, go = 0.f;
#pragma unroll
    for (int q = 0; q < 4; q++) {
        gi += red[q][b][jj];
        gf += red[q][b][4 + jj];
        gg += red[q][b][8 + jj];
        go += red[q][b][12 + jj];
    }
    const float* xr = g_xg + ((size_t)t * BB + b) * GG;
    int j = j0 + jj;
    gi += xr[j];
    gf += xr[HH + j];
    gg += xr[2 * HH + j];
    go += xr[3 * HH + j];

    float iv = 1.f / (1.f + expf(-gi));
    float fv = 1.f / (1.f + expf(-gf));
    float gv = tanhf(gg);
    float ov = 1.f / (1.f + expf(-go));

    int idx = b * HH + j;
    float cn = fv * g_c[idx] + iv * gv;
    g_c[idx] = cn;
    float hn = ov * tanhf(cn);
    hout[idx] = hn;
    g_hsum[idx] += hn;
}

// ---------------- 5. pooled = hsum/512 ; out = pooled @ W_fc^T + b_fc
__global__ void pool_fc_kernel(const float* __restrict__ Wfc,
                               const float* __restrict__ bfc,
                               float* __restrict__ out) {
    int b = blockIdx.x;
    __shared__ float sh[HH];
    int tid = threadIdx.x;   // 256
    for (int k = tid; k < HH; k += 256) sh[k] = g_hsum[b * HH + k];
    __syncthreads();
    int warp = tid >> 5, lane = tid & 31;
    for (int o = warp; o < OO; o += 8) {
        float a = 0.f;
        for (int k = lane; k < HH; k += 32) a += sh[k] * Wfc[o * HH + k];
#pragma unroll
        for (int s = 16; s; s >>= 1) a += __shfl_xor_sync(0xffffffffu, a, s);
        if (lane == 0) out[b * OO + o] = a * (1.f / 512.f) + bfc[o];
    }
}

extern "C" void kernel_launch(void* const* d_in, const int* in_sizes, int n_in,
                              void* d_out, int out_size) {
    const float* x    = (const float*)d_in[0];
    const float* Wemb = (const float*)d_in[1];
    const float* bemb = (const float*)d_in[2];
    const float* Wih  = (const float*)d_in[3];
    const float* Whh  = (const float*)d_in[4];
    const float* bih  = (const float*)d_in[5];
    const float* bhh  = (const float*)d_in[6];
    const float* Wfc  = (const float*)d_in[7];
    const float* bfc  = (const float*)d_in[8];
    float* out = (float*)d_out;

    fuse_weights_kernel<<<GG, 64>>>(Wih, Wemb, bemb, bih, bhh);

    dim3 xgrid((BB * TT) / 64, GG / 64);
    xg_kernel<<<xgrid, 256>>>(x);

    init_state_kernel<<<(BB * HH + 255) / 256, 256>>>();

    for (int t = 0; t < TT; t++) {
        lstm_step_kernel<<<HH / 4, 256>>>(Whh, t);
    }

    pool_fc_kernel<<<BB, 256>>>(Wfc, bfc, out);
}